// round 5
// baseline (speedup 1.0000x reference)
#include <cuda_runtime.h>
#include <cuda_bf16.h>
#include <cstdint>

// ---------------------------------------------------------------------------
// GraphSAGE, mma.sync bf16 hi/lo (3-product fp32-accurate), W-resident GEMM.
// Every layer GEMM: CTA = 256 thr (8 warps, 2m x 4n), tile M=64 x N=128,
// K=256 with W resident in SMEM and A double-buffered in 64-wide chunks.
// Final kernel fuses row L2-normalize + FC.
// ---------------------------------------------------------------------------

#define B_ROOT 16384
#define R1     49152
#define RSA    72            // A chunk row stride (bf16 elems)
#define RSW    264           // W / full-K row stride (bf16 elems)

// gemm_k smem offsets (bytes)
#define GA(buf) ((buf) * 18432)        // A buf: hi at +0 (9216), lo at +9216
#define G_WH   36864
#define G_WL   104448
#define G_SMEM 172032
// fc_k smem offsets
#define F_AH   0
#define F_AL   33792
#define F_WH   67584
#define F_WL   135168
#define F_SMEM 202752

// ---------------- scratch ----------------------------------------------------
__device__ float g_F0[B_ROOT * 256];
__device__ float g_F1[R1 * 256];
__device__ float g_G [B_ROOT * 256];
__device__ __nv_bfloat16 g_whi[5 * 32768];
__device__ __nv_bfloat16 g_wlo[5 * 32768];

// ---------------- helpers ----------------------------------------------------
__device__ __forceinline__ uint32_t smem_u32(const void* p) {
    uint32_t a;
    asm("{ .reg .u64 t; cvta.to.shared.u64 t, %1; cvt.u32.u64 %0, t; }"
        : "=r"(a) : "l"(p));
    return a;
}
__device__ __forceinline__ void split2(float a, float b, uint32_t& h, uint32_t& l) {
    __nv_bfloat16 ah = __float2bfloat16_rn(a), bh = __float2bfloat16_rn(b);
    __nv_bfloat16 al = __float2bfloat16_rn(a - __bfloat162float(ah));
    __nv_bfloat16 bl = __float2bfloat16_rn(b - __bfloat162float(bh));
    __nv_bfloat162 ph = __halves2bfloat162(ah, bh);
    __nv_bfloat162 pl = __halves2bfloat162(al, bl);
    h = *reinterpret_cast<uint32_t*>(&ph);
    l = *reinterpret_cast<uint32_t*>(&pl);
}
__device__ __forceinline__ void split8(const float* v, uint4& h4, uint4& l4) {
    uint32_t h[4], l[4];
#pragma unroll
    for (int i = 0; i < 4; ++i) split2(v[2 * i], v[2 * i + 1], h[i], l[i]);
    h4 = make_uint4(h[0], h[1], h[2], h[3]);
    l4 = make_uint4(l[0], l[1], l[2], l[3]);
}
__device__ __forceinline__ void mma16816(float* d, const uint32_t* a,
                                         uint32_t b0, uint32_t b1) {
    asm volatile(
        "mma.sync.aligned.m16n8k16.row.col.f32.bf16.bf16.f32 "
        "{%0,%1,%2,%3}, {%4,%5,%6,%7}, {%8,%9}, {%0,%1,%2,%3};"
        : "+f"(d[0]), "+f"(d[1]), "+f"(d[2]), "+f"(d[3])
        : "r"(a[0]), "r"(a[1]), "r"(a[2]), "r"(a[3]), "r"(b0), "r"(b1));
}
__device__ __forceinline__ void ldmx4(uint32_t* r, uint32_t a) {
    asm volatile("ldmatrix.sync.aligned.m8n8.x4.shared.b16 {%0,%1,%2,%3}, [%4];"
                 : "=r"(r[0]), "=r"(r[1]), "=r"(r[2]), "=r"(r[3]) : "r"(a));
}
__device__ __forceinline__ void cp16(uint32_t dst, const void* src) {
    asm volatile("cp.async.cg.shared.global [%0], [%1], 16;" :: "r"(dst), "l"(src));
}
#define CP_COMMIT() asm volatile("cp.async.commit_group;" ::: "memory")
#define CP_WAIT0()  asm volatile("cp.async.wait_group 0;"  ::: "memory")

// ---------------- weight pre-split --------------------------------------------
__global__ void conv_w(const float* __restrict__ a, const float* __restrict__ b,
                       const float* __restrict__ c, const float* __restrict__ d,
                       const float* __restrict__ e,
                       __nv_bfloat16* __restrict__ hi, __nv_bfloat16* __restrict__ lo) {
    int t = blockIdx.x * blockDim.x + threadIdx.x;
    const float* src[5] = {a, b, c, d, e};
    float x = src[t >> 15][t & 32767];
    __nv_bfloat16 h = __float2bfloat16_rn(x);
    hi[t] = h;
    lo[t] = __float2bfloat16_rn(x - __bfloat162float(h));
}

// ---------------- layer GEMM ---------------------------------------------------
// C[m0+m, col_off+n] = relu( rowop(A)[m] . W[n] + bias[n] ),  W: [128,256] hi/lo
// GATHER: 0 = A[idx[m]], 1 = mean_{j<KF} A[idx[m*KF+j]], 2 = A[m], 3 = mean3 A[3m+j]
template <int GATHER, int KF>
__global__ void __launch_bounds__(256)
gemm_k(const float* __restrict__ A, const int* __restrict__ idx,
       const __nv_bfloat16* __restrict__ w_hi, const __nv_bfloat16* __restrict__ w_lo,
       const float* __restrict__ bias,
       float* __restrict__ C, int ldc, int col_off)
{
    extern __shared__ char smem[];
    const uint32_t sb = smem_u32(smem);
    const int tid = threadIdx.x, lane = tid & 31, wid = tid >> 5;
    const int wm = wid >> 2, wn = wid & 3;
    const int lr = lane >> 2, lc = (lane & 3) * 2;
    const int g  = lane >> 3, lm = lane & 7;
    const int aro = ((g & 1) << 3) + lm, aco = (g >> 1) << 3;
    const int bro = ((g >> 1) << 3) + lm, bco = (g & 1) << 3;
    const int m0 = blockIdx.x * 64;
    const int r  = tid >> 2, cq = (tid & 3) * 16;

    // W: full-K resident, one cp.async burst (2 planes x 64KB)
#pragma unroll
    for (int i = 0; i < 32; ++i) {
        int o = tid + i * 256;
        int plane = o >> 12, ix = o & 4095;
        int row = ix >> 5, c8 = (ix & 31) * 8;
        const __nv_bfloat16* src = (plane ? w_lo : w_hi) + (size_t)row * 256 + c8;
        cp16(sb + (plane ? G_WL : G_WH) + (uint32_t)(row * RSW + c8) * 2, src);
    }
    CP_COMMIT();

    int rows[KF];
    if (GATHER == 0)      rows[0] = idx[m0 + r];
    else if (GATHER == 1) {
#pragma unroll
        for (int j = 0; j < KF; ++j) rows[j] = idx[(size_t)(m0 + r) * KF + j];
    } else if (GATHER == 2) rows[0] = m0 + r;
    else {
#pragma unroll
        for (int j = 0; j < KF; ++j) rows[j] = (m0 + r) * 3 + j;
    }

    float v[16];
    auto PREF = [&](int ch) {
        const int kb = ch * 64;
#pragma unroll
        for (int i = 0; i < 16; ++i) v[i] = 0.f;
#pragma unroll
        for (int j = 0; j < KF; ++j) {
            const float4* p = (const float4*)(A + (size_t)rows[j] * 256 + kb + cq);
#pragma unroll
            for (int q = 0; q < 4; ++q) {
                float4 f = __ldg(p + q);
                v[q * 4 + 0] += f.x; v[q * 4 + 1] += f.y;
                v[q * 4 + 2] += f.z; v[q * 4 + 3] += f.w;
            }
        }
    };
    auto STORE = [&](int buf) {
        const float s = 1.0f / (float)KF;
        float w[16];
#pragma unroll
        for (int i = 0; i < 16; ++i) w[i] = v[i] * s;
        uint4 h0, l0, h1, l1;
        split8(w, h0, l0);
        split8(w + 8, h1, l1);
        char* base = smem + GA(buf) + (size_t)(r * RSA + cq) * 2;
        *(uint4*)(base)              = h0;
        *(uint4*)(base + 16)         = h1;
        *(uint4*)(base + 9216)       = l0;
        *(uint4*)(base + 9216 + 16)  = l1;
    };

    float d[2][4][4];
#pragma unroll
    for (int i = 0; i < 2; ++i)
#pragma unroll
        for (int j = 0; j < 4; ++j)
#pragma unroll
            for (int k = 0; k < 4; ++k) d[i][j][k] = 0.f;

    PREF(0);
    STORE(0);
    CP_WAIT0();
    __syncthreads();

#pragma unroll
    for (int ch = 0; ch < 4; ++ch) {
        const int cb = ch & 1, nb = cb ^ 1;
        if (ch < 3) PREF(ch + 1);           // LDGs fly during the MMA burst
        const uint32_t aH = sb + GA(cb), aL = aH + 9216;
        const int kb = ch * 64;
#pragma unroll
        for (int ks = 0; ks < 4; ++ks) {
            uint32_t ah[2][4], al[2][4];
#pragma unroll
            for (int mi = 0; mi < 2; ++mi) {
                uint32_t ad = (uint32_t)((wm * 32 + mi * 16 + aro) * RSA
                                         + ks * 16 + aco) * 2;
                ldmx4(ah[mi], aH + ad);
                ldmx4(al[mi], aL + ad);
            }
            uint32_t bh[4][2], bl[4][2];
#pragma unroll
            for (int nip = 0; nip < 2; ++nip) {
                uint32_t bd = (uint32_t)((wn * 32 + nip * 16 + bro) * RSW
                                         + kb + ks * 16 + bco) * 2;
                uint32_t t4[4];
                ldmx4(t4, sb + G_WH + bd);
                bh[2 * nip][0] = t4[0]; bh[2 * nip][1] = t4[1];
                bh[2 * nip + 1][0] = t4[2]; bh[2 * nip + 1][1] = t4[3];
                ldmx4(t4, sb + G_WL + bd);
                bl[2 * nip][0] = t4[0]; bl[2 * nip][1] = t4[1];
                bl[2 * nip + 1][0] = t4[2]; bl[2 * nip + 1][1] = t4[3];
            }
#pragma unroll
            for (int ni = 0; ni < 4; ++ni)
#pragma unroll
                for (int mi = 0; mi < 2; ++mi) {
                    mma16816(d[mi][ni], ah[mi], bh[ni][0], bh[ni][1]);
                    mma16816(d[mi][ni], ah[mi], bl[ni][0], bl[ni][1]);
                    mma16816(d[mi][ni], al[mi], bh[ni][0], bh[ni][1]);
                }
        }
        if (ch < 3) STORE(nb);
        __syncthreads();
    }

    // epilogue: bias + relu
#pragma unroll
    for (int mi = 0; mi < 2; ++mi) {
        const int row = m0 + wm * 32 + mi * 16 + lr;
#pragma unroll
        for (int ni = 0; ni < 4; ++ni) {
            const int col = wn * 32 + ni * 8 + lc;
            const float b0 = __ldg(&bias[col]), b1 = __ldg(&bias[col + 1]);
            *(float2*)(C + (size_t)row * ldc + col_off + col) =
                make_float2(fmaxf(d[mi][ni][0] + b0, 0.f),
                            fmaxf(d[mi][ni][1] + b1, 0.f));
            *(float2*)(C + (size_t)(row + 8) * ldc + col_off + col) =
                make_float2(fmaxf(d[mi][ni][2] + b0, 0.f),
                            fmaxf(d[mi][ni][3] + b1, 0.f));
        }
    }
}

// ---------------- final: row L2-normalize + FC ---------------------------------
__global__ void __launch_bounds__(256)
fc_k(const float* __restrict__ Gm,
     const __nv_bfloat16* __restrict__ w_hi, const __nv_bfloat16* __restrict__ w_lo,
     const float* __restrict__ bias, float* __restrict__ C)
{
    extern __shared__ char smem[];
    const uint32_t sb = smem_u32(smem);
    const int tid = threadIdx.x, lane = tid & 31, wid = tid >> 5;
    const int wm = wid >> 2, wn = wid & 3;
    const int lr = lane >> 2, lc = (lane & 3) * 2;
    const int g  = lane >> 3, lm = lane & 7;
    const int aro = ((g & 1) << 3) + lm, aco = (g >> 1) << 3;
    const int bro = ((g >> 1) << 3) + lm, bco = (g & 1) << 3;
    const int m0 = blockIdx.x * 64;
    const int r  = tid >> 2, c0 = (tid & 3) * 64;

#pragma unroll
    for (int i = 0; i < 32; ++i) {
        int o = tid + i * 256;
        int plane = o >> 12, ix = o & 4095;
        int row = ix >> 5, c8 = (ix & 31) * 8;
        const __nv_bfloat16* src = (plane ? w_lo : w_hi) + (size_t)row * 256 + c8;
        cp16(sb + (plane ? F_WL : F_WH) + (uint32_t)(row * RSW + c8) * 2, src);
    }
    CP_COMMIT();

    // load full quarter-row, row sum-of-squares across the 4 owning threads
    float v[64];
    float ss = 0.f;
    const float4* p = (const float4*)(Gm + (size_t)(m0 + r) * 256 + c0);
#pragma unroll
    for (int q = 0; q < 16; ++q) {
        float4 f = __ldg(p + q);
        v[q * 4 + 0] = f.x; v[q * 4 + 1] = f.y;
        v[q * 4 + 2] = f.z; v[q * 4 + 3] = f.w;
        ss += f.x * f.x + f.y * f.y + f.z * f.z + f.w * f.w;
    }
    ss += __shfl_xor_sync(0xffffffffu, ss, 1);
    ss += __shfl_xor_sync(0xffffffffu, ss, 2);
    const float sc = 1.0f / fmaxf(sqrtf(ss), 1e-12f);
#pragma unroll
    for (int i = 0; i < 64; ++i) v[i] *= sc;
#pragma unroll
    for (int q = 0; q < 8; ++q) {
        uint4 h4, l4;
        split8(v + q * 8, h4, l4);
        size_t off = (size_t)(r * RSW + c0 + q * 8) * 2;
        *(uint4*)(smem + F_AH + off) = h4;
        *(uint4*)(smem + F_AL + off) = l4;
    }
    CP_WAIT0();
    __syncthreads();

    float d[2][4][4];
#pragma unroll
    for (int i = 0; i < 2; ++i)
#pragma unroll
        for (int j = 0; j < 4; ++j)
#pragma unroll
            for (int k = 0; k < 4; ++k) d[i][j][k] = 0.f;

#pragma unroll
    for (int ks = 0; ks < 16; ++ks) {
        uint32_t ah[2][4], al[2][4];
#pragma unroll
        for (int mi = 0; mi < 2; ++mi) {
            uint32_t ad = (uint32_t)((wm * 32 + mi * 16 + aro) * RSW
                                     + ks * 16 + aco) * 2;
            ldmx4(ah[mi], sb + F_AH + ad);
            ldmx4(al[mi], sb + F_AL + ad);
        }
        uint32_t bh[4][2], bl[4][2];
#pragma unroll
        for (int nip = 0; nip < 2; ++nip) {
            uint32_t bd = (uint32_t)((wn * 32 + nip * 16 + bro) * RSW
                                     + ks * 16 + bco) * 2;
            uint32_t t4[4];
            ldmx4(t4, sb + F_WH + bd);
            bh[2 * nip][0] = t4[0]; bh[2 * nip][1] = t4[1];
            bh[2 * nip + 1][0] = t4[2]; bh[2 * nip + 1][1] = t4[3];
            ldmx4(t4, sb + F_WL + bd);
            bl[2 * nip][0] = t4[0]; bl[2 * nip][1] = t4[1];
            bl[2 * nip + 1][0] = t4[2]; bl[2 * nip + 1][1] = t4[3];
        }
#pragma unroll
        for (int ni = 0; ni < 4; ++ni)
#pragma unroll
            for (int mi = 0; mi < 2; ++mi) {
                mma16816(d[mi][ni], ah[mi], bh[ni][0], bh[ni][1]);
                mma16816(d[mi][ni], ah[mi], bl[ni][0], bl[ni][1]);
                mma16816(d[mi][ni], al[mi], bh[ni][0], bh[ni][1]);
            }
    }

#pragma unroll
    for (int mi = 0; mi < 2; ++mi) {
        const int row = m0 + wm * 32 + mi * 16 + lr;
#pragma unroll
        for (int ni = 0; ni < 4; ++ni) {
            const int col = wn * 32 + ni * 8 + lc;
            const float b0 = __ldg(&bias[col]), b1 = __ldg(&bias[col + 1]);
            *(float2*)(C + (size_t)row * 128 + col) =
                make_float2(d[mi][ni][0] + b0, d[mi][ni][1] + b1);
            *(float2*)(C + (size_t)(row + 8) * 128 + col) =
                make_float2(d[mi][ni][2] + b0, d[mi][ni][3] + b1);
        }
    }
}

// ---------------------------------------------------------------------------
extern "C" void kernel_launch(void* const* d_in, const int* in_sizes, int n_in,
                              void* d_out, int out_size)
{
    const float* emb      = (const float*)d_in[0];
    const float* w_self0  = (const float*)d_in[1];
    const float* b_self0  = (const float*)d_in[2];
    const float* w_neigh0 = (const float*)d_in[3];
    const float* b_neigh0 = (const float*)d_in[4];
    const float* w_self1  = (const float*)d_in[5];
    const float* b_self1  = (const float*)d_in[6];
    const float* w_neigh1 = (const float*)d_in[7];
    const float* b_neigh1 = (const float*)d_in[8];
    const float* fc_w     = (const float*)d_in[9];
    const float* fc_b     = (const float*)d_in[10];
    const int*   nodeids  = (const int*)d_in[11];
    const int*   neigh1   = (const int*)d_in[12];
    const int*   neigh2   = (const int*)d_in[13];
    float*       out      = (float*)d_out;

    __nv_bfloat16 *WHI, *WLO;
    float *F0, *F1, *Gg;
    cudaGetSymbolAddress((void**)&WHI, g_whi);
    cudaGetSymbolAddress((void**)&WLO, g_wlo);
    cudaGetSymbolAddress((void**)&F0, g_F0);
    cudaGetSymbolAddress((void**)&F1, g_F1);
    cudaGetSymbolAddress((void**)&Gg, g_G);

    cudaFuncSetAttribute(gemm_k<0,1>, cudaFuncAttributeMaxDynamicSharedMemorySize, G_SMEM);
    cudaFuncSetAttribute(gemm_k<1,3>, cudaFuncAttributeMaxDynamicSharedMemorySize, G_SMEM);
    cudaFuncSetAttribute(gemm_k<1,5>, cudaFuncAttributeMaxDynamicSharedMemorySize, G_SMEM);
    cudaFuncSetAttribute(gemm_k<2,1>, cudaFuncAttributeMaxDynamicSharedMemorySize, G_SMEM);
    cudaFuncSetAttribute(gemm_k<3,3>, cudaFuncAttributeMaxDynamicSharedMemorySize, G_SMEM);
    cudaFuncSetAttribute(fc_k,        cudaFuncAttributeMaxDynamicSharedMemorySize, F_SMEM);

    conv_w<<<640, 256>>>(w_self0, w_neigh0, w_self1, w_neigh1, fc_w, WHI, WLO);

    // layer 0
    gemm_k<0,1><<<B_ROOT/64, 256, G_SMEM>>>(emb, nodeids, WHI, WLO,
                                            b_self0, F0, 256, 0);
    gemm_k<1,3><<<B_ROOT/64, 256, G_SMEM>>>(emb, neigh1, WHI + 32768, WLO + 32768,
                                            b_neigh0, F0, 256, 128);
    gemm_k<0,1><<<R1/64, 256, G_SMEM>>>(emb, neigh1, WHI, WLO,
                                        b_self0, F1, 256, 0);
    gemm_k<1,5><<<R1/64, 256, G_SMEM>>>(emb, neigh2, WHI + 32768, WLO + 32768,
                                        b_neigh0, F1, 256, 128);

    // layer 1
    gemm_k<2,1><<<B_ROOT/64, 256, G_SMEM>>>(F0, nullptr, WHI + 65536, WLO + 65536,
                                            b_self1, Gg, 256, 0);
    gemm_k<3,3><<<B_ROOT/64, 256, G_SMEM>>>(F1, nullptr, WHI + 98304, WLO + 98304,
                                            b_neigh1, Gg, 256, 128);

    // normalize + FC
    fc_k<<<B_ROOT/64, 256, F_SMEM>>>(Gg, WHI + 131072, WLO + 131072, fc_b, out);
}